// round 6
// baseline (speedup 1.0000x reference)
#include <cuda_runtime.h>

// EfficientGNN: 2-layer GCN + mean-over-nodes, algebraically collapsed.
// Separate arrays (co-location regressed in R3):
//   deg[c] += 1 per in-edge;  dinv = rsqrt(deg+1);  p = dinv*x
//   u[c] += p[r];  v[r] += dinv[c]           (random REDs)
//   s[i] = dinv*(p+u),  w[i] = dinv*(dinv+v)
//   t[f] = sum_i w[i]*relu(s[i]*W1[f]+b1[f]);  out = t@W2/N + b2

#define NMAX 100000
#define HID  128

// one contiguous zero block: [0:N) deg, [N:2N) u, [2N:3N) v, [3N:3N+HID) t
__device__ float g_z[3 * NMAX + HID];
__device__ float g_p[NMAX];
__device__ float g_dinv[NMAX];
__device__ int   g_ctr;

__global__ void k_deg(const int* __restrict__ col, int E) {
    float* deg = g_z;
    int i = blockIdx.x * blockDim.x + threadIdx.x;
    int e0 = i * 8;
    if (e0 + 7 < E) {
        int4 a = *reinterpret_cast<const int4*>(col + e0);
        int4 b = *reinterpret_cast<const int4*>(col + e0 + 4);
        atomicAdd(&deg[a.x], 1.0f); atomicAdd(&deg[a.y], 1.0f);
        atomicAdd(&deg[a.z], 1.0f); atomicAdd(&deg[a.w], 1.0f);
        atomicAdd(&deg[b.x], 1.0f); atomicAdd(&deg[b.y], 1.0f);
        atomicAdd(&deg[b.z], 1.0f); atomicAdd(&deg[b.w], 1.0f);
    } else {
        for (int e = e0; e < E; ++e) atomicAdd(&deg[col[e]], 1.0f);
    }
}

__global__ void k_dinv(const float* __restrict__ x, int n) {
    int i = blockIdx.x * blockDim.x + threadIdx.x;
    if (i == 0) g_ctr = 0;
    if (i < n) {
        float d = rsqrtf(g_z[i] + 1.0f);   // +1 self loop
        g_dinv[i] = d;
        g_p[i]    = d * x[i];
    }
}

__global__ void k_edge(const int* __restrict__ row, const int* __restrict__ col, int E) {
    float* u = g_z + NMAX;
    float* v = g_z + 2 * NMAX;
    int i = blockIdx.x * blockDim.x + threadIdx.x;
    int e0 = i * 8;
    if (e0 + 7 < E) {
        int4 ra = *reinterpret_cast<const int4*>(row + e0);
        int4 rb = *reinterpret_cast<const int4*>(row + e0 + 4);
        int4 ca = *reinterpret_cast<const int4*>(col + e0);
        int4 cb = *reinterpret_cast<const int4*>(col + e0 + 4);
        // all gathers first (MLP), then REDs
        float p0 = g_p[ra.x], p1 = g_p[ra.y], p2 = g_p[ra.z], p3 = g_p[ra.w];
        float p4 = g_p[rb.x], p5 = g_p[rb.y], p6 = g_p[rb.z], p7 = g_p[rb.w];
        float d0 = g_dinv[ca.x], d1 = g_dinv[ca.y], d2 = g_dinv[ca.z], d3 = g_dinv[ca.w];
        float d4 = g_dinv[cb.x], d5 = g_dinv[cb.y], d6 = g_dinv[cb.z], d7 = g_dinv[cb.w];
        atomicAdd(&u[ca.x], p0); atomicAdd(&u[ca.y], p1);
        atomicAdd(&u[ca.z], p2); atomicAdd(&u[ca.w], p3);
        atomicAdd(&u[cb.x], p4); atomicAdd(&u[cb.y], p5);
        atomicAdd(&u[cb.z], p6); atomicAdd(&u[cb.w], p7);
        atomicAdd(&v[ra.x], d0); atomicAdd(&v[ra.y], d1);
        atomicAdd(&v[ra.z], d2); atomicAdd(&v[ra.w], d3);
        atomicAdd(&v[rb.x], d4); atomicAdd(&v[rb.y], d5);
        atomicAdd(&v[rb.z], d6); atomicAdd(&v[rb.w], d7);
    } else {
        for (int e = e0; e < E; ++e) {
            int r = row[e], c = col[e];
            atomicAdd(&u[c], g_p[r]);
            atomicAdd(&v[r], g_dinv[c]);
        }
    }
}

// Warp-shuffle reduction + fused output matvec in the last block.
// blockDim.x == 256 (8 warps). Each lane owns features {lane, lane+32, lane+64, lane+96}.
__global__ void k_reduce_out(const float* __restrict__ W1, const float* __restrict__ b1,
                             const float* __restrict__ W2, const float* __restrict__ b2,
                             float* __restrict__ out, int n, int odim) {
    const float* u = g_z + NMAX;
    const float* v = g_z + 2 * NMAX;
    float* t = g_z + 3 * NMAX;

    int tid  = threadIdx.x;
    int lane = tid & 31;
    int gw   = (blockIdx.x * blockDim.x + tid) >> 5;
    int nw   = (gridDim.x * blockDim.x) >> 5;

    float W1f[4], b1f[4], acc[4];
    #pragma unroll
    for (int k = 0; k < 4; ++k) {
        W1f[k] = W1[lane + 32 * k];
        b1f[k] = b1[lane + 32 * k];
        acc[k] = 0.0f;
    }

    for (int base = gw * 32; base < n; base += nw * 32) {
        int i = base + lane;
        float s = 0.0f, w = 0.0f;
        if (i < n) {
            float d = g_dinv[i];
            s = d * (g_p[i] + u[i]);
            w = d * (d + v[i]);
        }
        #pragma unroll
        for (int j = 0; j < 32; ++j) {
            float sj = __shfl_sync(0xffffffffu, s, j);
            float wj = __shfl_sync(0xffffffffu, w, j);
            #pragma unroll
            for (int k = 0; k < 4; ++k)
                acc[k] += wj * fmaxf(fmaf(sj, W1f[k], b1f[k]), 0.0f);
        }
    }

    // block reduction: 8 warps -> 1
    __shared__ float red[8 * HID];
    int wl = tid >> 5;
    #pragma unroll
    for (int k = 0; k < 4; ++k) red[wl * HID + lane + 32 * k] = acc[k];
    __syncthreads();
    if (tid < HID) {
        float sum = 0.0f;
        #pragma unroll
        for (int w8 = 0; w8 < 8; ++w8) sum += red[w8 * HID + tid];
        atomicAdd(&t[tid], sum);
    }
    __threadfence();

    __shared__ int is_last;
    if (tid == 0)
        is_last = (atomicAdd(&g_ctr, 1) == (int)gridDim.x - 1);
    __syncthreads();

    if (is_last) {
        __shared__ float sh_t[HID];
        if (tid < HID) sh_t[tid] = __ldcg(&t[tid]);   // bypass L1: freshest L2 values
        __syncthreads();
        float inv_n = 1.0f / (float)n;
        for (int k = tid; k < odim; k += blockDim.x) {
            float a = 0.0f;
            #pragma unroll 16
            for (int f = 0; f < HID; ++f)
                a = fmaf(sh_t[f], W2[f * odim + k], a);
            out[k] = a * inv_n + b2[k];
        }
    }
}

extern "C" void kernel_launch(void* const* d_in, const int* in_sizes, int n_in,
                              void* d_out, int out_size) {
    const float* x   = (const float*)d_in[0];
    const int*   ei  = (const int*)  d_in[1];
    const float* W1  = (const float*)d_in[2];
    const float* b1  = (const float*)d_in[3];
    const float* W2  = (const float*)d_in[4];
    const float* b2  = (const float*)d_in[5];
    float*       out = (float*)d_out;

    int n = in_sizes[0];
    int E = in_sizes[1] / 2;
    const int* row = ei;
    const int* col = ei + E;
    int odim = out_size;

    void* zp = nullptr;
    cudaGetSymbolAddress(&zp, g_z);
    cudaMemsetAsync(zp, 0, (3 * NMAX + HID) * sizeof(float), 0);

    int tb = 256;
    int e8 = (E + 7) / 8;
    k_deg       <<<(e8 + tb - 1) / tb, tb>>>(col, E);
    k_dinv      <<<(n + tb - 1) / tb, tb>>>(x, n);
    k_edge      <<<(e8 + tb - 1) / tb, tb>>>(row, col, E);
    k_reduce_out<<<440, 256>>>(W1, b1, W2, b2, out, n, odim);
}

// round 8
// speedup vs baseline: 1.1518x; 1.1518x over previous
#include <cuda_runtime.h>

// EfficientGNN: 2-layer GCN + mean-over-nodes, algebraically collapsed,
// single persistent kernel with software grid barriers.
//   deg[c] += 1 per in-edge;  dinv = rsqrt(deg+1);  p = dinv*x
//   u[c] += p[r];  v[r] += dinv[c]           (random REDs, L2)
//   s[i] = dinv*(p+u),  w[i] = dinv*(dinv+v)
//   t[f] = sum_i w[i]*relu(s[i]*W1[f]+b1[f]);  out = t@W2/N + b2

#define NMAX 100000
#define HID  128
#define NB   512
#define TPB  256
#define NTHR (NB * TPB)

// one contiguous zero block (single memset each replay):
// [0:N) deg, [N:2N) u, [2N:3N) v, [3N:3N+HID) t, then 8 barrier counters
__device__ float g_z[3 * NMAX + HID + 8];
__device__ float g_p[NMAX];
__device__ float g_dinv[NMAX];

__device__ __forceinline__ void grid_bar(int idx) {
    __syncthreads();
    if (threadIdx.x == 0) {
        int* bar = (int*)(g_z + 3 * NMAX + HID);
        __threadfence();
        int a = atomicAdd(&bar[idx], 1);
        if (a + 1 < NB) {
            while (*((volatile int*)&bar[idx]) < NB) __nanosleep(64);
        }
        __threadfence();
    }
    __syncthreads();
}

__global__ void __launch_bounds__(TPB, 4)
k_all(const float* __restrict__ x, const int* __restrict__ row,
      const int* __restrict__ col,
      const float* __restrict__ W1, const float* __restrict__ b1,
      const float* __restrict__ W2, const float* __restrict__ b2,
      float* __restrict__ out, int n, int E, int odim) {
    float* deg = g_z;
    float* u   = g_z + NMAX;
    float* v   = g_z + 2 * NMAX;
    float* t   = g_z + 3 * NMAX;
    int tid = threadIdx.x;
    int gid = blockIdx.x * TPB + tid;

    // ---- P0: degree counts (1 RED/edge) ----
    for (int e0 = gid * 8; e0 < E; e0 += NTHR * 8) {
        if (e0 + 7 < E) {
            int4 a = *reinterpret_cast<const int4*>(col + e0);
            int4 b = *reinterpret_cast<const int4*>(col + e0 + 4);
            atomicAdd(&deg[a.x], 1.0f); atomicAdd(&deg[a.y], 1.0f);
            atomicAdd(&deg[a.z], 1.0f); atomicAdd(&deg[a.w], 1.0f);
            atomicAdd(&deg[b.x], 1.0f); atomicAdd(&deg[b.y], 1.0f);
            atomicAdd(&deg[b.z], 1.0f); atomicAdd(&deg[b.w], 1.0f);
        } else {
            for (int e = e0; e < E; ++e) atomicAdd(&deg[col[e]], 1.0f);
        }
    }
    grid_bar(0);

    // ---- P1: dinv, p ----
    for (int i = gid; i < n; i += NTHR) {
        float d = rsqrtf(deg[i] + 1.0f);     // +1 self loop
        g_dinv[i] = d;
        g_p[i]    = d * x[i];
    }
    grid_bar(1);

    // ---- P2: edge pass (2 gathers + 2 REDs per edge) ----
    for (int e0 = gid * 8; e0 < E; e0 += NTHR * 8) {
        if (e0 + 7 < E) {
            int4 ra = *reinterpret_cast<const int4*>(row + e0);
            int4 rb = *reinterpret_cast<const int4*>(row + e0 + 4);
            int4 ca = *reinterpret_cast<const int4*>(col + e0);
            int4 cb = *reinterpret_cast<const int4*>(col + e0 + 4);
            float p0 = g_p[ra.x], p1 = g_p[ra.y], p2 = g_p[ra.z], p3 = g_p[ra.w];
            float p4 = g_p[rb.x], p5 = g_p[rb.y], p6 = g_p[rb.z], p7 = g_p[rb.w];
            float d0 = g_dinv[ca.x], d1 = g_dinv[ca.y], d2 = g_dinv[ca.z], d3 = g_dinv[ca.w];
            float d4 = g_dinv[cb.x], d5 = g_dinv[cb.y], d6 = g_dinv[cb.z], d7 = g_dinv[cb.w];
            atomicAdd(&u[ca.x], p0); atomicAdd(&u[ca.y], p1);
            atomicAdd(&u[ca.z], p2); atomicAdd(&u[ca.w], p3);
            atomicAdd(&u[cb.x], p4); atomicAdd(&u[cb.y], p5);
            atomicAdd(&u[cb.z], p6); atomicAdd(&u[cb.w], p7);
            atomicAdd(&v[ra.x], d0); atomicAdd(&v[ra.y], d1);
            atomicAdd(&v[ra.z], d2); atomicAdd(&v[ra.w], d3);
            atomicAdd(&v[rb.x], d4); atomicAdd(&v[rb.y], d5);
            atomicAdd(&v[rb.z], d6); atomicAdd(&v[rb.w], d7);
        } else {
            for (int e = e0; e < E; ++e) {
                int r = row[e], c = col[e];
                atomicAdd(&u[c], g_p[r]);
                atomicAdd(&v[r], g_dinv[c]);
            }
        }
    }
    grid_bar(2);

    // ---- P3: t[f] = sum_i w[i]*relu(s[i]*W1[f]+b1[f]) ----
    // Block tile = 256 nodes; threads split as (feature f, node-half).
    {
        __shared__ float2 sh[TPB];        // {s, w} per node in tile
        __shared__ float  red[2 * HID];
        int f    = tid & (HID - 1);
        int half = tid >> 7;              // 0 or 1
        float W1f = W1[f];
        float b1f = b1[f];
        float a0 = 0.f, a1 = 0.f, a2 = 0.f, a3 = 0.f;
        for (int base = blockIdx.x * TPB; base < n; base += NB * TPB) {
            int i = base + tid;
            float2 swv = make_float2(0.0f, 0.0f);
            if (i < n) {
                float d = g_dinv[i];
                swv.x = d * (g_p[i] + u[i]);
                swv.y = d * (d + v[i]);
            }
            sh[tid] = swv;
            __syncthreads();
            const float2* shh = sh + half * HID;
            #pragma unroll
            for (int j = 0; j < HID; j += 4) {
                float2 e0 = shh[j + 0];
                float2 e1 = shh[j + 1];
                float2 e2 = shh[j + 2];
                float2 e3 = shh[j + 3];
                a0 += e0.y * fmaxf(fmaf(e0.x, W1f, b1f), 0.0f);
                a1 += e1.y * fmaxf(fmaf(e1.x, W1f, b1f), 0.0f);
                a2 += e2.y * fmaxf(fmaf(e2.x, W1f, b1f), 0.0f);
                a3 += e3.y * fmaxf(fmaf(e3.x, W1f, b1f), 0.0f);
            }
            __syncthreads();
        }
        red[half * HID + f] = (a0 + a1) + (a2 + a3);
        __syncthreads();
        if (tid < HID)
            atomicAdd(&t[tid], red[tid] + red[HID + tid]);
    }
    grid_bar(3);

    // ---- P4: out[k] = (t @ W2)[k]/n + b2[k], striped over all threads ----
    {
        __shared__ float sh_t[HID];
        if (gid < odim) {
            if (tid < HID) sh_t[tid] = __ldcg(&t[tid]);
            __syncthreads();
            float inv_n = 1.0f / (float)n;
            float a = 0.0f;
            #pragma unroll 16
            for (int f = 0; f < HID; ++f)
                a = fmaf(sh_t[f], W2[f * odim + gid], a);
            out[gid] = a * inv_n + b2[gid];
        }
    }
}

extern "C" void kernel_launch(void* const* d_in, const int* in_sizes, int n_in,
                              void* d_out, int out_size) {
    const float* x   = (const float*)d_in[0];
    const int*   ei  = (const int*)  d_in[1];
    const float* W1  = (const float*)d_in[2];
    const float* b1  = (const float*)d_in[3];
    const float* W2  = (const float*)d_in[4];
    const float* b2  = (const float*)d_in[5];
    float*       out = (float*)d_out;

    int n = in_sizes[0];
    int E = in_sizes[1] / 2;
    const int* row = ei;
    const int* col = ei + E;
    int odim = out_size;

    void* zp = nullptr;
    cudaGetSymbolAddress(&zp, g_z);
    cudaMemsetAsync(zp, 0, (3 * NMAX + HID + 8) * sizeof(float), 0);

    k_all<<<NB, TPB>>>(x, row, col, W1, b1, W2, b2, out, n, E, odim);
}

// round 10
// speedup vs baseline: 1.3414x; 1.1646x over previous
#include <cuda_runtime.h>

// EfficientGNN: 2-layer GCN + mean-over-nodes, algebraically collapsed.
// R2 multi-kernel skeleton (best: 52.9us) + fast reduce with fused output.
//   deg[c] += 1 per in-edge;  dinv = rsqrt(deg+1);  p = dinv*x
//   u[c] += p[r];  v[r] += dinv[c]           (random REDs, L2-resident)
//   s[i] = dinv*(p+u),  w[i] = dinv*(dinv+v)
//   t[f] = sum_i w[i]*relu(s[i]*W1[f]+b1[f]);  out = t@W2/N + b2

#define NMAX 100000
#define HID  128

// one contiguous zero block (single memset):
// [0:N) deg, [N:2N) u, [2N:3N) v, [3N:3N+HID) t, [+HID] ctr
__device__ float g_z[3 * NMAX + HID + 1];
__device__ float g_p[NMAX];
__device__ float g_dinv[NMAX];

__global__ void k_deg(const int* __restrict__ col, int E) {
    float* deg = g_z;
    int i = blockIdx.x * blockDim.x + threadIdx.x;
    int e0 = i * 8;
    if (e0 + 7 < E) {
        int4 a = *reinterpret_cast<const int4*>(col + e0);
        int4 b = *reinterpret_cast<const int4*>(col + e0 + 4);
        atomicAdd(&deg[a.x], 1.0f); atomicAdd(&deg[a.y], 1.0f);
        atomicAdd(&deg[a.z], 1.0f); atomicAdd(&deg[a.w], 1.0f);
        atomicAdd(&deg[b.x], 1.0f); atomicAdd(&deg[b.y], 1.0f);
        atomicAdd(&deg[b.z], 1.0f); atomicAdd(&deg[b.w], 1.0f);
    } else {
        for (int e = e0; e < E; ++e) atomicAdd(&deg[col[e]], 1.0f);
    }
}

__global__ void k_dinv(const float* __restrict__ x, int n) {
    int i = blockIdx.x * blockDim.x + threadIdx.x;
    if (i < n) {
        float d = rsqrtf(g_z[i] + 1.0f);   // +1 self loop
        g_dinv[i] = d;
        g_p[i]    = d * x[i];
    }
}

__global__ void k_edge(const int* __restrict__ row, const int* __restrict__ col, int E) {
    float* u = g_z + NMAX;
    float* v = g_z + 2 * NMAX;
    int i = blockIdx.x * blockDim.x + threadIdx.x;
    int e0 = i * 8;
    if (e0 + 7 < E) {
        int4 ra = *reinterpret_cast<const int4*>(row + e0);
        int4 rb = *reinterpret_cast<const int4*>(row + e0 + 4);
        int4 ca = *reinterpret_cast<const int4*>(col + e0);
        int4 cb = *reinterpret_cast<const int4*>(col + e0 + 4);
        // all gathers first (MLP), then REDs
        float p0 = g_p[ra.x], p1 = g_p[ra.y], p2 = g_p[ra.z], p3 = g_p[ra.w];
        float p4 = g_p[rb.x], p5 = g_p[rb.y], p6 = g_p[rb.z], p7 = g_p[rb.w];
        float d0 = g_dinv[ca.x], d1 = g_dinv[ca.y], d2 = g_dinv[ca.z], d3 = g_dinv[ca.w];
        float d4 = g_dinv[cb.x], d5 = g_dinv[cb.y], d6 = g_dinv[cb.z], d7 = g_dinv[cb.w];
        atomicAdd(&u[ca.x], p0); atomicAdd(&u[ca.y], p1);
        atomicAdd(&u[ca.z], p2); atomicAdd(&u[ca.w], p3);
        atomicAdd(&u[cb.x], p4); atomicAdd(&u[cb.y], p5);
        atomicAdd(&u[cb.z], p6); atomicAdd(&u[cb.w], p7);
        atomicAdd(&v[ra.x], d0); atomicAdd(&v[ra.y], d1);
        atomicAdd(&v[ra.z], d2); atomicAdd(&v[ra.w], d3);
        atomicAdd(&v[rb.x], d4); atomicAdd(&v[rb.y], d5);
        atomicAdd(&v[rb.z], d6); atomicAdd(&v[rb.w], d7);
    } else {
        for (int e = e0; e < E; ++e) {
            int r = row[e], c = col[e];
            atomicAdd(&u[c], g_p[r]);
            atomicAdd(&v[r], g_dinv[c]);
        }
    }
}

// One 256-node tile per block. threads = (feature f in [0,128), node-half).
// Last block computes out = t@W2/n + b2.
__global__ void __launch_bounds__(256)
k_reduce_out(const float* __restrict__ W1, const float* __restrict__ b1,
             const float* __restrict__ W2, const float* __restrict__ b2,
             float* __restrict__ out, int n, int odim) {
    const float* u = g_z + NMAX;
    const float* v = g_z + 2 * NMAX;
    float* t   = g_z + 3 * NMAX;
    int*   ctr = (int*)(g_z + 3 * NMAX + HID);

    __shared__ float2 sh[256];         // {s, w}
    __shared__ float  red[2 * HID];
    int tid  = threadIdx.x;
    int f    = tid & (HID - 1);
    int half = tid >> 7;

    int i = blockIdx.x * 256 + tid;
    float2 swv = make_float2(0.0f, 0.0f);
    if (i < n) {
        float d = g_dinv[i];
        swv.x = d * (g_p[i] + u[i]);
        swv.y = d * (d + v[i]);
    }
    sh[tid] = swv;
    __syncthreads();

    float W1f = W1[f];
    float b1f = b1[f];
    float a0 = 0.f, a1 = 0.f, a2 = 0.f, a3 = 0.f;
    const float2* shh = sh + half * HID;
    #pragma unroll
    for (int j = 0; j < HID; j += 4) {
        float2 e0 = shh[j + 0];
        float2 e1 = shh[j + 1];
        float2 e2 = shh[j + 2];
        float2 e3 = shh[j + 3];
        a0 += e0.y * fmaxf(fmaf(e0.x, W1f, b1f), 0.0f);
        a1 += e1.y * fmaxf(fmaf(e1.x, W1f, b1f), 0.0f);
        a2 += e2.y * fmaxf(fmaf(e2.x, W1f, b1f), 0.0f);
        a3 += e3.y * fmaxf(fmaf(e3.x, W1f, b1f), 0.0f);
    }
    red[half * HID + f] = (a0 + a1) + (a2 + a3);
    __syncthreads();
    if (tid < HID)
        atomicAdd(&t[tid], red[tid] + red[HID + tid]);
    __threadfence();

    __shared__ int is_last;
    if (tid == 0)
        is_last = (atomicAdd(ctr, 1) == (int)gridDim.x - 1);
    __syncthreads();

    if (is_last) {
        __shared__ float sh_t[HID];
        if (tid < HID) sh_t[tid] = __ldcg(&t[tid]);
        __syncthreads();
        float inv_n = 1.0f / (float)n;
        for (int k = tid; k < odim; k += blockDim.x) {
            float a = 0.0f;
            #pragma unroll 16
            for (int ff = 0; ff < HID; ++ff)
                a = fmaf(sh_t[ff], W2[ff * odim + k], a);
            out[k] = a * inv_n + b2[k];
        }
    }
}

extern "C" void kernel_launch(void* const* d_in, const int* in_sizes, int n_in,
                              void* d_out, int out_size) {
    const float* x   = (const float*)d_in[0];
    const int*   ei  = (const int*)  d_in[1];
    const float* W1  = (const float*)d_in[2];
    const float* b1  = (const float*)d_in[3];
    const float* W2  = (const float*)d_in[4];
    const float* b2  = (const float*)d_in[5];
    float*       out = (float*)d_out;

    int n = in_sizes[0];
    int E = in_sizes[1] / 2;
    const int* row = ei;
    const int* col = ei + E;
    int odim = out_size;

    void* zp = nullptr;
    cudaGetSymbolAddress(&zp, g_z);
    cudaMemsetAsync(zp, 0, (3 * NMAX + HID + 1) * sizeof(float), 0);

    int tb = 256;
    int e8 = (E + 7) / 8;
    k_deg       <<<(e8 + tb - 1) / tb, tb>>>(col, E);
    k_dinv      <<<(n + tb - 1) / tb, tb>>>(x, n);
    k_edge      <<<(e8 + tb - 1) / tb, tb>>>(row, col, E);
    k_reduce_out<<<(n + 255) / 256, 256>>>(W1, b1, W2, b2, out, n, odim);
}

// round 12
// speedup vs baseline: 1.4483x; 1.0797x over previous
#include <cuda_runtime.h>

// EfficientGNN: 2-layer GCN + mean-over-nodes, algebraically collapsed.
// Multi-kernel, fence-free (fusion/threadfence regressed in R4/R8/R10).
//   deg[c] += 1 per in-edge;  dinv = rsqrt(deg+1);  p = dinv*x
//   u[c] += p[r];  v[r] += dinv[c]           (random REDs, L2-resident)
//   s[i] = dinv*(p+u),  w[i] = dinv*(dinv+v)
//   t[f] = sum_i w[i]*relu(s[i]*W1[f]+b1[f]);  out = t@W2/N + b2

#define NMAX 100000
#define HID  128

// one contiguous zero block (single memset):
// [0:N) deg, [N:2N) u, [2N:3N) v, [3N:3N+HID) t
__device__ float g_z[3 * NMAX + HID];
__device__ float g_p[NMAX];
__device__ float g_dinv[NMAX];

__global__ void k_deg(const int* __restrict__ col, int E) {
    float* deg = g_z;
    int i = blockIdx.x * blockDim.x + threadIdx.x;
    int e0 = i * 8;
    if (e0 + 7 < E) {
        int4 a = *reinterpret_cast<const int4*>(col + e0);
        int4 b = *reinterpret_cast<const int4*>(col + e0 + 4);
        atomicAdd(&deg[a.x], 1.0f); atomicAdd(&deg[a.y], 1.0f);
        atomicAdd(&deg[a.z], 1.0f); atomicAdd(&deg[a.w], 1.0f);
        atomicAdd(&deg[b.x], 1.0f); atomicAdd(&deg[b.y], 1.0f);
        atomicAdd(&deg[b.z], 1.0f); atomicAdd(&deg[b.w], 1.0f);
    } else {
        for (int e = e0; e < E; ++e) atomicAdd(&deg[col[e]], 1.0f);
    }
}

__global__ void k_dinv(const float* __restrict__ x, int n) {
    int i = blockIdx.x * blockDim.x + threadIdx.x;
    if (i < n) {
        float d = rsqrtf(g_z[i] + 1.0f);   // +1 self loop
        g_dinv[i] = d;
        g_p[i]    = d * x[i];
    }
}

__global__ void k_edge(const int* __restrict__ row, const int* __restrict__ col, int E) {
    float* u = g_z + NMAX;
    float* v = g_z + 2 * NMAX;
    int i = blockIdx.x * blockDim.x + threadIdx.x;
    int e0 = i * 8;
    if (e0 + 7 < E) {
        int4 ra = *reinterpret_cast<const int4*>(row + e0);
        int4 rb = *reinterpret_cast<const int4*>(row + e0 + 4);
        int4 ca = *reinterpret_cast<const int4*>(col + e0);
        int4 cb = *reinterpret_cast<const int4*>(col + e0 + 4);
        // all gathers first (MLP), then REDs
        float p0 = g_p[ra.x], p1 = g_p[ra.y], p2 = g_p[ra.z], p3 = g_p[ra.w];
        float p4 = g_p[rb.x], p5 = g_p[rb.y], p6 = g_p[rb.z], p7 = g_p[rb.w];
        float d0 = g_dinv[ca.x], d1 = g_dinv[ca.y], d2 = g_dinv[ca.z], d3 = g_dinv[ca.w];
        float d4 = g_dinv[cb.x], d5 = g_dinv[cb.y], d6 = g_dinv[cb.z], d7 = g_dinv[cb.w];
        atomicAdd(&u[ca.x], p0); atomicAdd(&u[ca.y], p1);
        atomicAdd(&u[ca.z], p2); atomicAdd(&u[ca.w], p3);
        atomicAdd(&u[cb.x], p4); atomicAdd(&u[cb.y], p5);
        atomicAdd(&u[cb.z], p6); atomicAdd(&u[cb.w], p7);
        atomicAdd(&v[ra.x], d0); atomicAdd(&v[ra.y], d1);
        atomicAdd(&v[ra.z], d2); atomicAdd(&v[ra.w], d3);
        atomicAdd(&v[rb.x], d4); atomicAdd(&v[rb.y], d5);
        atomicAdd(&v[rb.z], d6); atomicAdd(&v[rb.w], d7);
    } else {
        for (int e = e0; e < E; ++e) {
            int r = row[e], c = col[e];
            atomicAdd(&u[c], g_p[r]);
            atomicAdd(&v[r], g_dinv[c]);
        }
    }
}

// One 256-node tile per block; threads = (feature f, node-half).
// Inner loop reads TWO nodes per LDS.128 (float4 over {s,w} pairs).
__global__ void __launch_bounds__(256)
k_reduce(const float* __restrict__ W1, const float* __restrict__ b1, int n) {
    const float* u = g_z + NMAX;
    const float* v = g_z + 2 * NMAX;
    float* t = g_z + 3 * NMAX;

    __shared__ float2 sh[256];         // {s, w} per node
    __shared__ float  red[2 * HID];
    int tid  = threadIdx.x;
    int f    = tid & (HID - 1);
    int half = tid >> 7;

    int i = blockIdx.x * 256 + tid;
    float2 swv = make_float2(0.0f, 0.0f);
    if (i < n) {
        float d = g_dinv[i];
        swv.x = d * (g_p[i] + u[i]);
        swv.y = d * (d + v[i]);
    }
    sh[tid] = swv;
    __syncthreads();

    float W1f = W1[f];
    float b1f = b1[f];
    float a0 = 0.f, a1 = 0.f, a2 = 0.f, a3 = 0.f;
    const float4* shh = reinterpret_cast<const float4*>(sh + half * HID);  // 64 float4 = 128 nodes
    #pragma unroll
    for (int j = 0; j < 64; j += 4) {
        float4 q0 = shh[j + 0];    // {s0,w0,s1,w1}
        float4 q1 = shh[j + 1];
        float4 q2 = shh[j + 2];
        float4 q3 = shh[j + 3];
        a0 += q0.y * fmaxf(fmaf(q0.x, W1f, b1f), 0.0f);
        a1 += q0.w * fmaxf(fmaf(q0.z, W1f, b1f), 0.0f);
        a2 += q1.y * fmaxf(fmaf(q1.x, W1f, b1f), 0.0f);
        a3 += q1.w * fmaxf(fmaf(q1.z, W1f, b1f), 0.0f);
        a0 += q2.y * fmaxf(fmaf(q2.x, W1f, b1f), 0.0f);
        a1 += q2.w * fmaxf(fmaf(q2.z, W1f, b1f), 0.0f);
        a2 += q3.y * fmaxf(fmaf(q3.x, W1f, b1f), 0.0f);
        a3 += q3.w * fmaxf(fmaf(q3.z, W1f, b1f), 0.0f);
    }
    red[half * HID + f] = (a0 + a1) + (a2 + a3);
    __syncthreads();
    if (tid < HID)
        atomicAdd(&t[tid], red[tid] + red[HID + tid]);
}

// 4 blocks x 128 threads: one output element per thread, W2 reads coalesced.
__global__ void __launch_bounds__(128)
k_out(const float* __restrict__ W2, const float* __restrict__ b2,
      float* __restrict__ out, int n, int odim) {
    const float* t = g_z + 3 * NMAX;
    __shared__ float sh_t[HID];
    int tid = threadIdx.x;
    sh_t[tid] = t[tid];
    __syncthreads();
    int k = blockIdx.x * 128 + tid;
    if (k < odim) {
        float a = 0.0f;
        #pragma unroll 16
        for (int f = 0; f < HID; ++f)
            a = fmaf(sh_t[f], W2[f * odim + k], a);
        out[k] = a * (1.0f / (float)n) + b2[k];
    }
}

extern "C" void kernel_launch(void* const* d_in, const int* in_sizes, int n_in,
                              void* d_out, int out_size) {
    const float* x   = (const float*)d_in[0];
    const int*   ei  = (const int*)  d_in[1];
    const float* W1  = (const float*)d_in[2];
    const float* b1  = (const float*)d_in[3];
    const float* W2  = (const float*)d_in[4];
    const float* b2  = (const float*)d_in[5];
    float*       out = (float*)d_out;

    int n = in_sizes[0];
    int E = in_sizes[1] / 2;
    const int* row = ei;
    const int* col = ei + E;
    int odim = out_size;

    void* zp = nullptr;
    cudaGetSymbolAddress(&zp, g_z);
    cudaMemsetAsync(zp, 0, (3 * NMAX + HID) * sizeof(float), 0);

    int tb = 256;
    int e8 = (E + 7) / 8;
    k_deg   <<<(e8 + tb - 1) / tb, tb>>>(col, E);
    k_dinv  <<<(n + tb - 1) / tb, tb>>>(x, n);
    k_edge  <<<(e8 + tb - 1) / tb, tb>>>(row, col, E);
    k_reduce<<<(n + 255) / 256, 256>>>(W1, b1, n);
    k_out   <<<(odim + 127) / 128, 128>>>(W2, b2, out, n, odim);
}